// round 13
// baseline (speedup 1.0000x reference)
#include <cuda_runtime.h>

#define NB 296            // 148 SMs x 2 blocks -> perfectly uniform wave
#define NT 256
#define HOIST_MAX 4096

__device__ float        g_partials[NB];
__device__ unsigned int g_bar;   // monotonic ticket counter (never reset)

__global__ void __launch_bounds__(NT, 2)
ril_fused_kernel(const float* __restrict__ x,
                 const float* __restrict__ weights,
                 const float* __restrict__ min_vals,
                 const float* __restrict__ max_vals,
                 const int* __restrict__ start_pos,
                 const int* __restrict__ offsets,
                 const int* __restrict__ sizes,
                 const int* __restrict__ out_mask,
                 float* __restrict__ out,
                 int B, int D, int G, int Wn, int OUTN, int total)
{
    // Shared: G floats (min_vals) | G int4 ({max,start,off,size}) | hoisted mask
    extern __shared__ float smv[];
    int4*  stab  = (int4*)(smv + G);
    float* smask = (float*)(stab + G);

    const int lane = threadIdx.x & 31;
    const int w    = threadIdx.x >> 5;
    const float inv_b = 1.0f / (float)B;

    // ---- Vectorized table preload (1.25 LDG/entry instead of 5) ----
    if ((G & 3) == 0) {
        const float4* mv4 = (const float4*)min_vals;
        const float4* mx4 = (const float4*)max_vals;
        const int4*   sp4 = (const int4*)start_pos;
        const int4*   of4 = (const int4*)offsets;
        const int4*   sz4 = (const int4*)sizes;
        for (int i = threadIdx.x; i < (G >> 2); i += NT) {
            const float4 mv = __ldg(&mv4[i]);
            const float4 mx = __ldg(&mx4[i]);
            const int4   sp = __ldg(&sp4[i]);
            const int4   of = __ldg(&of4[i]);
            const int4   sz = __ldg(&sz4[i]);
            const int ib = i * 4;
            smv[ib + 0] = mv.x; smv[ib + 1] = mv.y; smv[ib + 2] = mv.z; smv[ib + 3] = mv.w;
            stab[ib + 0] = make_int4(__float_as_int(mx.x), sp.x, of.x, sz.x);
            stab[ib + 1] = make_int4(__float_as_int(mx.y), sp.y, of.y, sz.y);
            stab[ib + 2] = make_int4(__float_as_int(mx.z), sp.z, of.z, sz.z);
            stab[ib + 3] = make_int4(__float_as_int(mx.w), sp.w, of.w, sz.w);
        }
    } else {
        for (int i = threadIdx.x; i < G; i += NT) {
            smv[i] = __ldg(&min_vals[i]);
            stab[i] = make_int4(__float_as_int(__ldg(&max_vals[i])),
                                __ldg(&start_pos[i]), __ldg(&offsets[i]), __ldg(&sizes[i]));
        }
    }

    // Hoist this block's out_mask slice as 0/1 floats
    const int per = (total + (int)gridDim.x - 1) / (int)gridDim.x;
    const int j0  = blockIdx.x * per;
    const int j1  = min(j0 + per, total);
    const bool hoist = (per <= HOIST_MAX);
    if (hoist) {
        for (int j = j0 + threadIdx.x; j < j1; j += NT) {
            float m = 0.0f;
            if (j < OUTN) m = (__ldg(&out_mask[j]) != 0) ? 1.0f : 0.0f;
            smask[j - j0] = m;
        }
    }
    __syncthreads();

    const float m0 = smv[0];
    const float mL = smv[G - 1];
    const float inv_step = (mL > m0) ? (float)(G - 1) / (mL - m0) : 0.0f;

    // ---- Phase 1: contiguous per-block column slice (uniform per-SM load) ----
    const int ncols = (D + (int)gridDim.x - 1) / (int)gridDim.x;
    const int c0    = blockIdx.x * ncols;
    const int c1    = min(c0 + ncols, D);
    float acc = 0.0f;
    for (int col = c0 + threadIdx.x; col < c1; col += NT) {
        float s = 0.0f;
        #pragma unroll 8
        for (int b = 0; b < B; ++b)
            s += __ldg(x + (size_t)b * D + col);
        const float vv = s * inv_b;

        // searchsorted(min_vals, vv, 'right') - 1: interpolation + predicated fixup
        int g;
        if (!(vv >= m0)) {
            g = -1;
        } else {
            int gg = (int)floorf((vv - m0) * inv_step);
            gg = min(max(gg, 0), G - 1);
            gg -= (smv[gg] > vv) ? 1 : 0;
            gg -= (gg > 0 && smv[gg] > vv) ? 1 : 0;
            gg += (gg + 1 < G && smv[gg + 1] <= vv) ? 1 : 0;
            gg += (gg + 1 < G && smv[gg + 1] <= vv) ? 1 : 0;
            gg = max(gg, 0);
            bool ok = (smv[gg] <= vv) && (gg + 1 >= G || smv[gg + 1] > vv);
            if (!ok) {                     // general fallback (non-uniform grids)
                int lo = 0, hi = G;
                while (lo < hi) {
                    int mid = (lo + hi) >> 1;
                    if (smv[mid] <= vv) lo = mid + 1; else hi = mid;
                }
                gg = lo - 1;
            }
            g = gg;
        }

        const int gc = min(max(g, 0), G - 1);
        const int4 e = stab[gc];
        const float mx = __int_as_float(e.x);
        bool in_range = (g >= 0) && (vv >= smv[gc]) && (vv <= mx);
        int pos = col - e.y;
        bool valid = in_range && (pos >= 0) && (pos < e.w);
        int widx = min(max(e.z + pos, 0), Wn - 1);
        float wv = valid ? __ldg(&weights[widx]) : 0.0f;
        acc += vv * wv;
    }

    // ---- Block reduce ----
    #pragma unroll
    for (int o = 16; o > 0; o >>= 1)
        acc += __shfl_down_sync(0xffffffffu, acc, o);
    __shared__ float red[NT / 32];
    if (lane == 0) red[w] = acc;
    __syncthreads();
    if (threadIdx.x == 0) {
        float p = 0.0f;
        #pragma unroll
        for (int k = 0; k < NT / 32; ++k) p += red[k];
        g_partials[blockIdx.x] = p;
    }

    // ---- Device-wide ticket barrier (monotonic; survives graph replays) ----
    if (threadIdx.x == 0) {
        __threadfence();
        unsigned int arrival = atomicAdd(&g_bar, 1u) + 1u;
        unsigned int target  = ((arrival - 1u) / gridDim.x + 1u) * gridDim.x;
        unsigned int c;
        do {
            asm volatile("ld.acquire.gpu.u32 %0, [%1];" : "=r"(c) : "l"(&g_bar));
        } while (c < target);
    }
    __syncthreads();

    // ---- Phase 2: all blocks sum partials with a fixed deterministic tree ----
    float a2 = 0.0f;
    for (int i = threadIdx.x; i < (int)gridDim.x; i += NT)
        a2 += *(volatile float*)&g_partials[i];
    #pragma unroll
    for (int o = 16; o > 0; o >>= 1)
        a2 += __shfl_down_sync(0xffffffffu, a2, o);
    __shared__ float red2[NT / 32];
    __shared__ float s_val;
    if (lane == 0) red2[w] = a2;
    __syncthreads();
    if (threadIdx.x == 0) {
        float s = 0.0f;
        #pragma unroll
        for (int k = 0; k < NT / 32; ++k) s += red2[k];
        s_val = s;
    }
    __syncthreads();
    const float s = s_val;

    // ---- Output: masked broadcast from shared ----
    if (hoist) {
        for (int j = j0 + threadIdx.x; j < j1; j += NT)
            out[j] = s * smask[j - j0];
    } else {
        for (int j = j0 + threadIdx.x; j < j1; j += NT) {
            float o = 0.0f;
            if (j < OUTN) o = (__ldg(&out_mask[j]) != 0) ? s : 0.0f;
            out[j] = o;
        }
    }
}

extern "C" void kernel_launch(void* const* d_in, const int* in_sizes, int n_in,
                              void* d_out, int out_size)
{
    const float* x        = (const float*)d_in[0];
    const float* weights  = (const float*)d_in[1];
    const float* min_vals = (const float*)d_in[2];
    const float* max_vals = (const float*)d_in[3];
    const int*   start_p  = (const int*)d_in[4];
    const int*   offsets  = (const int*)d_in[5];
    const int*   sizes    = (const int*)d_in[6];
    const int*   out_mask = (const int*)d_in[7];
    float* out = (float*)d_out;

    int G  = in_sizes[2];
    int Wn = in_sizes[1];
    int D  = Wn / G;
    int B  = in_sizes[0] / D;
    int OUTN = in_sizes[7];

    int per = (out_size + NB - 1) / NB;
    int hoist_elems = (per <= HOIST_MAX) ? per : 0;
    size_t shmem = (size_t)G * (sizeof(float) + sizeof(int4))
                 + (size_t)hoist_elems * sizeof(float);

    ril_fused_kernel<<<NB, NT, shmem>>>(
        x, weights, min_vals, max_vals, start_p, offsets, sizes,
        out_mask, out, B, D, G, Wn, OUTN, out_size);
}

// round 14
// speedup vs baseline: 1.1528x; 1.1528x over previous
#include <cuda_runtime.h>

#define NB 256
#define NT 256
#define HOIST_MAX 4096

__device__ float        g_partials[NB];
__device__ unsigned int g_bar;   // monotonic ticket counter (never reset)

__global__ void __launch_bounds__(NT, 2)
ril_fused_kernel(const float* __restrict__ x,
                 const float* __restrict__ weights,
                 const float* __restrict__ min_vals,
                 const float* __restrict__ max_vals,
                 const int* __restrict__ start_pos,
                 const int* __restrict__ offsets,
                 const int* __restrict__ sizes,
                 const int* __restrict__ out_mask,
                 float* __restrict__ out,
                 int B, int D, int G, int Wn, int OUTN, int total)
{
    // Shared: G floats (min_vals) | G int4 ({max,start,off,size}) | hoisted mask
    extern __shared__ float smv[];
    int4*  stab  = (int4*)(smv + G);
    float* smask = (float*)(stab + G);

    const int lane = threadIdx.x & 31;
    const int w    = threadIdx.x >> 5;
    const float inv_b = 1.0f / (float)B;

    // Scalar table preload (keeps register count low — vector version regressed)
    for (int i = threadIdx.x; i < G; i += NT) {
        smv[i] = __ldg(&min_vals[i]);
        int4 e;
        e.x = __float_as_int(__ldg(&max_vals[i]));
        e.y = __ldg(&start_pos[i]);
        e.z = __ldg(&offsets[i]);
        e.w = __ldg(&sizes[i]);
        stab[i] = e;
    }

    // Hoist this block's out_mask slice to shared as 0/1 floats (pre-barrier)
    const int per = (total + (int)gridDim.x - 1) / (int)gridDim.x;
    const int j0  = blockIdx.x * per;
    const int j1  = min(j0 + per, total);
    const bool hoist = (per <= HOIST_MAX);
    if (hoist) {
        for (int j = j0 + threadIdx.x; j < j1; j += NT) {
            float m = 0.0f;
            if (j < OUTN) m = (__ldg(&out_mask[j]) != 0) ? 1.0f : 0.0f;
            smask[j - j0] = m;
        }
    }
    __syncthreads();

    const float m0 = smv[0];
    const float mL = smv[G - 1];
    const float inv_step = (mL > m0) ? (float)(G - 1) / (mL - m0) : 0.0f;

    // ---- Phase 1: one column per thread, grid-stride ----
    float acc = 0.0f;
    const int stride = (int)gridDim.x * NT;
    for (int col = blockIdx.x * NT + threadIdx.x; col < D; col += stride) {
        float s = 0.0f;
        #pragma unroll 8
        for (int b = 0; b < B; ++b)
            s += __ldg(x + (size_t)b * D + col);
        const float vv = s * inv_b;

        // searchsorted(min_vals, vv, 'right') - 1: interpolation + predicated fixup
        int g;
        if (!(vv >= m0)) {
            g = -1;
        } else {
            int gg = (int)floorf((vv - m0) * inv_step);
            gg = min(max(gg, 0), G - 1);
            // single predicated step each direction (uniform grids need <=1)
            gg -= (smv[gg] > vv) ? 1 : 0;
            gg += (gg + 1 < G && smv[gg + 1] <= vv) ? 1 : 0;
            gg = max(gg, 0);
            bool ok = (smv[gg] <= vv) && (gg + 1 >= G || smv[gg + 1] > vv);
            if (!ok) {                     // general fallback (non-uniform grids)
                int lo = 0, hi = G;
                while (lo < hi) {
                    int mid = (lo + hi) >> 1;
                    if (smv[mid] <= vv) lo = mid + 1; else hi = mid;
                }
                gg = lo - 1;
            }
            g = gg;
        }

        const int gc = min(max(g, 0), G - 1);
        const int4 e = stab[gc];
        const float mx = __int_as_float(e.x);
        bool in_range = (g >= 0) && (vv >= smv[gc]) && (vv <= mx);
        int pos = col - e.y;
        bool valid = in_range && (pos >= 0) && (pos < e.w);
        int widx = min(max(e.z + pos, 0), Wn - 1);
        float wv = valid ? __ldg(&weights[widx]) : 0.0f;
        acc += vv * wv;
    }

    // ---- Block reduce ----
    #pragma unroll
    for (int o = 16; o > 0; o >>= 1)
        acc += __shfl_down_sync(0xffffffffu, acc, o);
    __shared__ float red[NT / 32];
    if (lane == 0) red[w] = acc;
    __syncthreads();
    if (threadIdx.x == 0) {
        float p = 0.0f;
        #pragma unroll
        for (int k = 0; k < NT / 32; ++k) p += red[k];
        g_partials[blockIdx.x] = p;
    }

    // ---- Device-wide ticket barrier (monotonic; survives graph replays) ----
    if (threadIdx.x == 0) {
        __threadfence();
        unsigned int arrival = atomicAdd(&g_bar, 1u) + 1u;
        unsigned int target  = ((arrival - 1u) / gridDim.x + 1u) * gridDim.x;
        unsigned int c;
        do {
            asm volatile("ld.acquire.gpu.u32 %0, [%1];" : "=r"(c) : "l"(&g_bar));
        } while (c < target);
    }
    __syncthreads();

    // ---- Phase 2: sum partials (NB == NT: one partial per thread) ----
    float a2 = 0.0f;
    if (threadIdx.x < (int)gridDim.x)
        a2 = *(volatile float*)&g_partials[threadIdx.x];
    for (int i = NT + threadIdx.x; i < (int)gridDim.x; i += NT)   // only if grid > NT
        a2 += *(volatile float*)&g_partials[i];
    #pragma unroll
    for (int o = 16; o > 0; o >>= 1)
        a2 += __shfl_down_sync(0xffffffffu, a2, o);
    __shared__ float red2[NT / 32];
    __shared__ float s_val;
    if (lane == 0) red2[w] = a2;
    __syncthreads();
    if (threadIdx.x == 0) {
        float s = 0.0f;
        #pragma unroll
        for (int k = 0; k < NT / 32; ++k) s += red2[k];
        s_val = s;
    }
    __syncthreads();
    const float s = s_val;

    // ---- Output: masked broadcast from shared (no global mask reload) ----
    if (hoist) {
        for (int j = j0 + threadIdx.x; j < j1; j += NT)
            out[j] = s * smask[j - j0];
    } else {
        for (int j = j0 + threadIdx.x; j < j1; j += NT) {
            float o = 0.0f;
            if (j < OUTN) o = (__ldg(&out_mask[j]) != 0) ? s : 0.0f;
            out[j] = o;
        }
    }
}

extern "C" void kernel_launch(void* const* d_in, const int* in_sizes, int n_in,
                              void* d_out, int out_size)
{
    const float* x        = (const float*)d_in[0];
    const float* weights  = (const float*)d_in[1];
    const float* min_vals = (const float*)d_in[2];
    const float* max_vals = (const float*)d_in[3];
    const int*   start_p  = (const int*)d_in[4];
    const int*   offsets  = (const int*)d_in[5];
    const int*   sizes    = (const int*)d_in[6];
    const int*   out_mask = (const int*)d_in[7];
    float* out = (float*)d_out;

    int G  = in_sizes[2];
    int Wn = in_sizes[1];
    int D  = Wn / G;
    int B  = in_sizes[0] / D;
    int OUTN = in_sizes[7];

    int per = (out_size + NB - 1) / NB;
    int hoist_elems = (per <= HOIST_MAX) ? per : 0;
    size_t shmem = (size_t)G * (sizeof(float) + sizeof(int4))
                 + (size_t)hoist_elems * sizeof(float);

    ril_fused_kernel<<<NB, NT, shmem>>>(
        x, weights, min_vals, max_vals, start_p, offsets, sizes,
        out_mask, out, B, D, G, Wn, OUTN, out_size);
}